// round 5
// baseline (speedup 1.0000x reference)
#include <cuda_runtime.h>
#include <math.h>
#include <stdint.h>

// SlotAttention on GB300 — Round 3: eliminate KV projection GEMMs entirely.
//   logits = (q·Wk)·x̂ᵀ      (fold Wq,Wk into Wqk = Wqᵀ·Wk, once)
//   gi     = (attn·x̂)·(w_ih·Wv)ᵀ   (fold Wv into W_iv = w_ih·Wv, once)
// Only x̂ = LN(inputs) is materialized (fp32). All fp32.

#define Bb 64
#define Nn 4096
#define Dd 256
#define Kk 15
#define Hh 512
#define BN_TOT (Bb * Nn)   // 262144
#define BK_TOT (Bb * Kk)   // 960
#define NBLK 32

// ---------------- scratch (static device memory) ----------------
__device__ float g_xln[(size_t)BN_TOT * Dd];   // 256 MiB LN(inputs)
__device__ float g_wqk[Dd * Dd];               // [e][d] layout for A@Wᵀ gemm
__device__ float g_wiv[3 * Dd * Dd];           // [g][e] = w_ih·Wv
__device__ float g_slots[BK_TOT * Dd];
__device__ float g_slots_prev[BK_TOT * Dd];
__device__ float g_sln[BK_TOT * Dd];
__device__ float g_q[BK_TOT * Dd];             // q' = sln·Wqk
__device__ float g_attn[(size_t)Bb * Kk * Nn];
__device__ float g_part[Bb * Kk * NBLK];
__device__ float g_invsum[BK_TOT];
__device__ float g_updpart[8 * BK_TOT * Dd];
__device__ float g_updates[BK_TOT * Dd];       // u' = attn_norm·x̂
__device__ float g_gi[BK_TOT * 3 * Dd];
__device__ float g_gh[BK_TOT * 3 * Dd];
__device__ float g_h1[BK_TOT * Hh];

// ---------------- helpers ----------------
__device__ __forceinline__ float warp_sum(float v) {
#pragma unroll
    for (int o = 16; o > 0; o >>= 1) v += __shfl_xor_sync(0xffffffffu, v, o);
    return v;
}
__device__ __forceinline__ float sigmoidf_(float x) { return 1.0f / (1.0f + expf(-x)); }

// ---------------- generic row LayerNorm (M x 256) ----------------
__global__ void ln_apply_kernel(const float* __restrict__ x, float* __restrict__ y,
                                const float* __restrict__ w, const float* __restrict__ bb,
                                int M) {
    int row = blockIdx.x * 8 + threadIdx.y;
    if (row >= M) return;
    int lane = threadIdx.x;
    const float* xr = x + (size_t)row * Dd;
    float v[8];
    float s = 0.f, s2 = 0.f;
#pragma unroll
    for (int j = 0; j < 8; j++) {
        v[j] = xr[j * 32 + lane];
        s += v[j]; s2 += v[j] * v[j];
    }
    s = warp_sum(s); s2 = warp_sum(s2);
    float m = s * (1.0f / 256.0f);
    float rs = rsqrtf(s2 * (1.0f / 256.0f) - m * m + 1e-5f);
    float* yr = y + (size_t)row * Dd;
#pragma unroll
    for (int j = 0; j < 8; j++) {
        int dd = j * 32 + lane;
        yr[dd] = (v[j] - m) * rs * w[dd] + bb[dd];
    }
}

// ---------------- precompute: C[e][d] = sum_j X[j][e] * Y[j][d]  (XᵀY) ----------------
__global__ __launch_bounds__(256) void atb_kernel(const float* __restrict__ X,
                                                  const float* __restrict__ Y,
                                                  float* __restrict__ C) {
    __shared__ float Xs[16][68];
    __shared__ float Ys[16][68];
    int e0 = blockIdx.x * 64, d0 = blockIdx.y * 64;
    int tid = threadIdx.x;
    int row_t = tid >> 4, col_t = tid & 15;
    int jr = tid >> 4, c4 = (tid & 15) << 2;

    float acc[4][4];
#pragma unroll
    for (int i = 0; i < 4; i++)
#pragma unroll
        for (int j = 0; j < 4; j++) acc[i][j] = 0.f;

    for (int jb = 0; jb < 256; jb += 16) {
        float4 xv = *(const float4*)(X + (size_t)(jb + jr) * Dd + e0 + c4);
        Xs[jr][c4 + 0] = xv.x; Xs[jr][c4 + 1] = xv.y;
        Xs[jr][c4 + 2] = xv.z; Xs[jr][c4 + 3] = xv.w;
        float4 yv = *(const float4*)(Y + (size_t)(jb + jr) * Dd + d0 + c4);
        Ys[jr][c4 + 0] = yv.x; Ys[jr][c4 + 1] = yv.y;
        Ys[jr][c4 + 2] = yv.z; Ys[jr][c4 + 3] = yv.w;
        __syncthreads();
#pragma unroll
        for (int k = 0; k < 16; k++) {
#pragma unroll
            for (int i = 0; i < 4; i++)
#pragma unroll
                for (int j = 0; j < 4; j++)
                    acc[i][j] += Xs[k][row_t * 4 + i] * Ys[k][col_t * 4 + j];
        }
        __syncthreads();
    }
#pragma unroll
    for (int i = 0; i < 4; i++)
#pragma unroll
        for (int j = 0; j < 4; j++)
            C[(size_t)(e0 + row_t * 4 + i) * Dd + d0 + col_t * 4 + j] = acc[i][j];
}

// ---------------- precompute: C[g][e] = sum_d A[g][d] * B[d][e]  (A·B) ----------------
__global__ __launch_bounds__(256) void ab_kernel(const float* __restrict__ A,
                                                 const float* __restrict__ B,
                                                 float* __restrict__ C) {
    __shared__ float As[16][68];
    __shared__ float Bs[16][68];
    int g0 = blockIdx.x * 64, e0 = blockIdx.y * 64;
    int tid = threadIdx.x;
    int row_t = tid >> 4, col_t = tid & 15;
    int r = tid >> 2, k4 = (tid & 3) << 2;
    int jr = tid >> 4, c4 = (tid & 15) << 2;

    float acc[4][4];
#pragma unroll
    for (int i = 0; i < 4; i++)
#pragma unroll
        for (int j = 0; j < 4; j++) acc[i][j] = 0.f;

    for (int db = 0; db < 256; db += 16) {
        float4 av = *(const float4*)(A + (size_t)(g0 + r) * Dd + db + k4);
        As[k4 + 0][r] = av.x; As[k4 + 1][r] = av.y;
        As[k4 + 2][r] = av.z; As[k4 + 3][r] = av.w;
        float4 bv = *(const float4*)(B + (size_t)(db + jr) * Dd + e0 + c4);
        Bs[jr][c4 + 0] = bv.x; Bs[jr][c4 + 1] = bv.y;
        Bs[jr][c4 + 2] = bv.z; Bs[jr][c4 + 3] = bv.w;
        __syncthreads();
#pragma unroll
        for (int k = 0; k < 16; k++) {
#pragma unroll
            for (int i = 0; i < 4; i++)
#pragma unroll
                for (int j = 0; j < 4; j++)
                    acc[i][j] += As[k][row_t * 4 + i] * Bs[k][col_t * 4 + j];
        }
        __syncthreads();
    }
#pragma unroll
    for (int i = 0; i < 4; i++)
#pragma unroll
        for (int j = 0; j < 4; j++)
            C[(size_t)(g0 + row_t * 4 + i) * Dd + e0 + col_t * 4 + j] = acc[i][j];
}

// ---------------- slots init ----------------
__global__ void slots_init_kernel(const float* __restrict__ mu,
                                  const float* __restrict__ ls,
                                  const float* __restrict__ noise) {
    int i = blockIdx.x * 256 + threadIdx.x;
    int kd = i % (Kk * Dd);
    g_slots[i] = mu[kd] + expf(ls[kd]) * noise[i];
}

// ---------------- small GEMM: C[M][Nc] = A[M][Kc] @ W[Nc][Kc]^T ----------------
__global__ __launch_bounds__(256) void small_gemm_kernel(
    const float* __restrict__ A, const float* __restrict__ W,
    const float* __restrict__ bias, const float* __restrict__ res,
    float* __restrict__ C, int Kc, int Nc, int mode)
{
    __shared__ float As[16][68];
    __shared__ float Bs[16][68];
    int m0 = blockIdx.x * 64, n0 = blockIdx.y * 64;
    int tid = threadIdx.x;
    int row_t = tid >> 4, col_t = tid & 15;
    int r = tid >> 2, k4 = (tid & 3) << 2;

    float acc[4][4];
#pragma unroll
    for (int i = 0; i < 4; i++)
#pragma unroll
        for (int j = 0; j < 4; j++) acc[i][j] = 0.f;

    for (int kb = 0; kb < Kc; kb += 16) {
        float4 av = *(const float4*)(A + (size_t)(m0 + r) * Kc + kb + k4);
        As[k4 + 0][r] = av.x; As[k4 + 1][r] = av.y;
        As[k4 + 2][r] = av.z; As[k4 + 3][r] = av.w;
        float4 wv = *(const float4*)(W + (size_t)(n0 + r) * Kc + kb + k4);
        Bs[k4 + 0][r] = wv.x; Bs[k4 + 1][r] = wv.y;
        Bs[k4 + 2][r] = wv.z; Bs[k4 + 3][r] = wv.w;
        __syncthreads();
#pragma unroll
        for (int k = 0; k < 16; k++) {
            float4 a4 = *(const float4*)&As[k][row_t * 4];
            float4 b4 = *(const float4*)&Bs[k][col_t * 4];
            float a[4] = {a4.x, a4.y, a4.z, a4.w};
            float bb[4] = {b4.x, b4.y, b4.z, b4.w};
#pragma unroll
            for (int i = 0; i < 4; i++)
#pragma unroll
                for (int j = 0; j < 4; j++) acc[i][j] += a[i] * bb[j];
        }
        __syncthreads();
    }
#pragma unroll
    for (int i = 0; i < 4; i++) {
        int m = m0 + row_t * 4 + i;
        float vals[4];
#pragma unroll
        for (int j = 0; j < 4; j++) {
            int col = n0 + col_t * 4 + j;
            float val = acc[i][j];
            if (mode & 1) val += bias[col];
            if (mode & 4) val += res[(size_t)m * Nc + col];
            if (mode & 2) val = fmaxf(val, 0.f);
            vals[j] = val;
        }
        *(float4*)(C + (size_t)m * Nc + n0 + col_t * 4) =
            make_float4(vals[0], vals[1], vals[2], vals[3]);
    }
}

// ---------------- logits (q'·x̂ᵀ) + softmax(over slots) + partial rowsums ----------------
__global__ __launch_bounds__(128) void logits_softmax_kernel(
    const float* __restrict__ q, const float* __restrict__ xln,
    float* __restrict__ attn, float* __restrict__ partsum)
{
    int b = blockIdx.y;
    int nblk = blockIdx.x;
    int tid = threadIdx.x;
    int n = nblk * 128 + tid;

    __shared__ float4 qs[Kk][64];
    const float4* qb = (const float4*)(q + (size_t)b * Kk * Dd);
    for (int i = tid; i < Kk * 64; i += 128) qs[i >> 6][i & 63] = qb[i];
    __syncthreads();

    const float4* kr = (const float4*)(xln + ((size_t)b * Nn + n) * Dd);
    float l[Kk];
#pragma unroll
    for (int s = 0; s < Kk; s++) l[s] = 0.f;
    for (int d4 = 0; d4 < 64; d4++) {
        float4 kv = kr[d4];
#pragma unroll
        for (int s = 0; s < Kk; s++) {
            float4 qv = qs[s][d4];
            l[s] += qv.x * kv.x + qv.y * kv.y + qv.z * kv.z + qv.w * kv.w;
        }
    }
    float mx = -1e30f;
#pragma unroll
    for (int s = 0; s < Kk; s++) { l[s] *= 0.0625f; mx = fmaxf(mx, l[s]); }
    float sum = 0.f;
#pragma unroll
    for (int s = 0; s < Kk; s++) { l[s] = expf(l[s] - mx); sum += l[s]; }
    float inv = 1.0f / sum;
#pragma unroll
    for (int s = 0; s < Kk; s++) {
        l[s] *= inv;
        attn[((size_t)b * Kk + s) * Nn + n] = l[s];
    }
    __shared__ float red2[Kk][4];
    int warp = tid >> 5, lane = tid & 31;
#pragma unroll
    for (int s = 0; s < Kk; s++) {
        float w = warp_sum(l[s]);
        if (lane == 0) red2[s][warp] = w;
    }
    __syncthreads();
    if (tid < Kk) {
        float s4 = red2[tid][0] + red2[tid][1] + red2[tid][2] + red2[tid][3];
        partsum[(b * Kk + tid) * NBLK + nblk] = s4;
    }
}

__global__ void invsum_kernel() {
    int i = blockIdx.x * 128 + threadIdx.x;
    if (i < BK_TOT) {
        float s = 0.f;
#pragma unroll
        for (int j = 0; j < NBLK; j++) s += g_part[i * NBLK + j];
        g_invsum[i] = 1.0f / (s + 1e-8f);
    }
}

// ---------------- u' = attn_norm @ x̂, split over 8 n-chunks ----------------
__global__ __launch_bounds__(256) void updates_partial_kernel(
    const float* __restrict__ attn, const float* __restrict__ xln)
{
    int b = blockIdx.y, chunk = blockIdx.x;
    int d = threadIdx.x;
    __shared__ float as[Kk][128];
    __shared__ float inv[Kk];
    if (d < Kk) inv[d] = g_invsum[b * Kk + d];
    float acc[Kk];
#pragma unroll
    for (int s = 0; s < Kk; s++) acc[s] = 0.f;
    int nbase = chunk * 512;
    for (int nt = 0; nt < 512; nt += 128) {
        __syncthreads();
        for (int i = d; i < Kk * 128; i += 256) {
            int s = i >> 7, nn = i & 127;
            as[s][nn] = attn[((size_t)b * Kk + s) * Nn + nbase + nt + nn] * inv[s];
        }
        __syncthreads();
#pragma unroll 4
        for (int j = 0; j < 128; j++) {
            float vv = xln[((size_t)b * Nn + nbase + nt + j) * Dd + d];
#pragma unroll
            for (int s = 0; s < Kk; s++) acc[s] += as[s][j] * vv;
        }
    }
    float* p = g_updpart + (size_t)chunk * (BK_TOT * Dd) + (size_t)(b * Kk) * Dd + d;
#pragma unroll
    for (int s = 0; s < Kk; s++) p[s * Dd] = acc[s];
}

__global__ void updates_reduce_kernel() {
    int i = blockIdx.x * 256 + threadIdx.x;
    float s = 0.f;
#pragma unroll
    for (int c = 0; c < 8; c++) s += g_updpart[(size_t)c * (BK_TOT * Dd) + i];
    g_updates[i] = s;
}

// ---------------- GRU gates ----------------
__global__ void gru_gate_kernel() {
    int i = blockIdx.x * 256 + threadIdx.x;
    int row = i >> 8, d = i & 255;
    const float* gi = g_gi + (size_t)row * 768;
    const float* gh = g_gh + (size_t)row * 768;
    float r = sigmoidf_(gi[d] + gh[d]);
    float z = sigmoidf_(gi[256 + d] + gh[256 + d]);
    float nn = tanhf(gi[512 + d] + r * gh[512 + d]);
    float h = g_slots_prev[i];
    g_slots[i] = (1.0f - z) * nn + z * h;
}

__global__ void copy_kernel(const float* __restrict__ src, float* __restrict__ dst, int n) {
    int i = blockIdx.x * 256 + threadIdx.x;
    if (i < n) dst[i] = src[i];
}

// ---------------- host orchestration ----------------
extern "C" void kernel_launch(void* const* d_in, const int* in_sizes, int n_in,
                              void* d_out, int out_size) {
    const float* inputs        = (const float*)d_in[0];
    const float* slot_noise    = (const float*)d_in[1];
    const float* slots_mu      = (const float*)d_in[2];
    const float* slots_logsig  = (const float*)d_in[3];
    const float* Wq            = (const float*)d_in[4];
    const float* Wk            = (const float*)d_in[5];
    const float* Wv            = (const float*)d_in[6];
    const float* w_ih          = (const float*)d_in[7];
    const float* w_hh          = (const float*)d_in[8];
    const float* b_ih          = (const float*)d_in[9];
    const float* b_hh          = (const float*)d_in[10];
    const float* mlp_w1        = (const float*)d_in[11];
    const float* mlp_b1        = (const float*)d_in[12];
    const float* mlp_w2        = (const float*)d_in[13];
    const float* mlp_b2        = (const float*)d_in[14];
    const float* ln_in_w       = (const float*)d_in[15];
    const float* ln_in_b       = (const float*)d_in[16];
    const float* ln_s_w        = (const float*)d_in[17];
    const float* ln_s_b        = (const float*)d_in[18];
    const float* ln_m_w        = (const float*)d_in[19];
    const float* ln_m_b        = (const float*)d_in[20];
    float* out = (float*)d_out;

    float *p_xln, *p_wqk, *p_wiv, *p_attn, *p_part, *p_sln, *p_q, *p_slots,
          *p_prev, *p_upd, *p_gi, *p_gh, *p_h1;
    cudaGetSymbolAddress((void**)&p_xln, g_xln);
    cudaGetSymbolAddress((void**)&p_wqk, g_wqk);
    cudaGetSymbolAddress((void**)&p_wiv, g_wiv);
    cudaGetSymbolAddress((void**)&p_attn, g_attn);
    cudaGetSymbolAddress((void**)&p_part, g_part);
    cudaGetSymbolAddress((void**)&p_sln, g_sln);
    cudaGetSymbolAddress((void**)&p_q, g_q);
    cudaGetSymbolAddress((void**)&p_slots, g_slots);
    cudaGetSymbolAddress((void**)&p_prev, g_slots_prev);
    cudaGetSymbolAddress((void**)&p_upd, g_updates);
    cudaGetSymbolAddress((void**)&p_gi, g_gi);
    cudaGetSymbolAddress((void**)&p_gh, g_gh);
    cudaGetSymbolAddress((void**)&p_h1, g_h1);

    // x̂ = LN(inputs); weight folds; slots init
    ln_apply_kernel<<<BN_TOT / 8, dim3(32, 8)>>>(inputs, p_xln, ln_in_w, ln_in_b, BN_TOT);
    atb_kernel<<<dim3(4, 4), 256>>>(Wk, Wq, p_wqk);        // Wqk[e][d] = Σ_j Wk[j,e]·Wq[j,d]
    ab_kernel<<<dim3(12, 4), 256>>>(w_ih, Wv, p_wiv);      // W_iv[g][e] = Σ_d w_ih[g,d]·Wv[d,e]
    slots_init_kernel<<<BK_TOT, 256>>>(slots_mu, slots_logsig, slot_noise);

    for (int it = 0; it < 3; it++) {
        copy_kernel<<<960, 256>>>(p_slots, p_prev, BK_TOT * Dd);
        ln_apply_kernel<<<120, dim3(32, 8)>>>(p_slots, p_sln, ln_s_w, ln_s_b, BK_TOT);
        small_gemm_kernel<<<dim3(15, 4), 256>>>(p_sln, p_wqk, nullptr, nullptr, p_q, 256, 256, 0);
        logits_softmax_kernel<<<dim3(NBLK, Bb), 128>>>(p_q, p_xln, p_attn, p_part);
        invsum_kernel<<<8, 128>>>();
        updates_partial_kernel<<<dim3(8, Bb), 256>>>(p_attn, p_xln);
        updates_reduce_kernel<<<960, 256>>>();
        small_gemm_kernel<<<dim3(15, 12), 256>>>(p_upd, p_wiv, b_ih, nullptr, p_gi, 256, 768, 1);
        small_gemm_kernel<<<dim3(15, 12), 256>>>(p_prev, w_hh, b_hh, nullptr, p_gh, 256, 768, 1);
        gru_gate_kernel<<<960, 256>>>();
        ln_apply_kernel<<<120, dim3(32, 8)>>>(p_slots, p_sln, ln_m_w, ln_m_b, BK_TOT);
        small_gemm_kernel<<<dim3(15, 8), 256>>>(p_sln, mlp_w1, mlp_b1, nullptr, p_h1, 256, 512, 1 | 2);
        small_gemm_kernel<<<dim3(15, 4), 256>>>(p_h1, mlp_w2, mlp_b2, p_slots, p_slots, 512, 256, 1 | 4);
    }

    // final attention
    ln_apply_kernel<<<120, dim3(32, 8)>>>(p_slots, p_sln, ln_s_w, ln_s_b, BK_TOT);
    small_gemm_kernel<<<dim3(15, 4), 256>>>(p_sln, p_wqk, nullptr, nullptr, p_q, 256, 256, 0);
    logits_softmax_kernel<<<dim3(NBLK, Bb), 128>>>(p_q, p_xln, out + BK_TOT * Dd, p_part);
    copy_kernel<<<960, 256>>>(p_slots, out, BK_TOT * Dd);
}

// round 6
// speedup vs baseline: 1.0044x; 1.0044x over previous
#include <cuda_runtime.h>
#include <math.h>
#include <stdint.h>

// SlotAttention on GB300 — Round 3: eliminate KV projection GEMMs entirely.
//   logits = (q·Wk)·x̂ᵀ      (fold Wq,Wk into Wqk = Wqᵀ·Wk, once)
//   gi     = (attn·x̂)·(w_ih·Wv)ᵀ   (fold Wv into W_iv = w_ih·Wv, once)
// Only x̂ = LN(inputs) is materialized (fp32). All fp32.

#define Bb 64
#define Nn 4096
#define Dd 256
#define Kk 15
#define Hh 512
#define BN_TOT (Bb * Nn)   // 262144
#define BK_TOT (Bb * Kk)   // 960
#define NBLK 32

// ---------------- scratch (static device memory) ----------------
__device__ float g_xln[(size_t)BN_TOT * Dd];   // 256 MiB LN(inputs)
__device__ float g_wqk[Dd * Dd];               // [e][d] layout for A@Wᵀ gemm
__device__ float g_wiv[3 * Dd * Dd];           // [g][e] = w_ih·Wv
__device__ float g_slots[BK_TOT * Dd];
__device__ float g_slots_prev[BK_TOT * Dd];
__device__ float g_sln[BK_TOT * Dd];
__device__ float g_q[BK_TOT * Dd];             // q' = sln·Wqk
__device__ float g_attn[(size_t)Bb * Kk * Nn];
__device__ float g_part[Bb * Kk * NBLK];
__device__ float g_invsum[BK_TOT];
__device__ float g_updpart[8 * BK_TOT * Dd];
__device__ float g_updates[BK_TOT * Dd];       // u' = attn_norm·x̂
__device__ float g_gi[BK_TOT * 3 * Dd];
__device__ float g_gh[BK_TOT * 3 * Dd];
__device__ float g_h1[BK_TOT * Hh];

// ---------------- helpers ----------------
__device__ __forceinline__ float warp_sum(float v) {
#pragma unroll
    for (int o = 16; o > 0; o >>= 1) v += __shfl_xor_sync(0xffffffffu, v, o);
    return v;
}
__device__ __forceinline__ float sigmoidf_(float x) { return 1.0f / (1.0f + expf(-x)); }

// ---------------- generic row LayerNorm (M x 256) ----------------
__global__ void ln_apply_kernel(const float* __restrict__ x, float* __restrict__ y,
                                const float* __restrict__ w, const float* __restrict__ bb,
                                int M) {
    int row = blockIdx.x * 8 + threadIdx.y;
    if (row >= M) return;
    int lane = threadIdx.x;
    const float* xr = x + (size_t)row * Dd;
    float v[8];
    float s = 0.f, s2 = 0.f;
#pragma unroll
    for (int j = 0; j < 8; j++) {
        v[j] = xr[j * 32 + lane];
        s += v[j]; s2 += v[j] * v[j];
    }
    s = warp_sum(s); s2 = warp_sum(s2);
    float m = s * (1.0f / 256.0f);
    float rs = rsqrtf(s2 * (1.0f / 256.0f) - m * m + 1e-5f);
    float* yr = y + (size_t)row * Dd;
#pragma unroll
    for (int j = 0; j < 8; j++) {
        int dd = j * 32 + lane;
        yr[dd] = (v[j] - m) * rs * w[dd] + bb[dd];
    }
}

// ---------------- precompute: C[e][d] = sum_j X[j][e] * Y[j][d]  (XᵀY) ----------------
__global__ __launch_bounds__(256) void atb_kernel(const float* __restrict__ X,
                                                  const float* __restrict__ Y,
                                                  float* __restrict__ C) {
    __shared__ float Xs[16][68];
    __shared__ float Ys[16][68];
    int e0 = blockIdx.x * 64, d0 = blockIdx.y * 64;
    int tid = threadIdx.x;
    int row_t = tid >> 4, col_t = tid & 15;
    int jr = tid >> 4, c4 = (tid & 15) << 2;

    float acc[4][4];
#pragma unroll
    for (int i = 0; i < 4; i++)
#pragma unroll
        for (int j = 0; j < 4; j++) acc[i][j] = 0.f;

    for (int jb = 0; jb < 256; jb += 16) {
        float4 xv = *(const float4*)(X + (size_t)(jb + jr) * Dd + e0 + c4);
        Xs[jr][c4 + 0] = xv.x; Xs[jr][c4 + 1] = xv.y;
        Xs[jr][c4 + 2] = xv.z; Xs[jr][c4 + 3] = xv.w;
        float4 yv = *(const float4*)(Y + (size_t)(jb + jr) * Dd + d0 + c4);
        Ys[jr][c4 + 0] = yv.x; Ys[jr][c4 + 1] = yv.y;
        Ys[jr][c4 + 2] = yv.z; Ys[jr][c4 + 3] = yv.w;
        __syncthreads();
#pragma unroll
        for (int k = 0; k < 16; k++) {
#pragma unroll
            for (int i = 0; i < 4; i++)
#pragma unroll
                for (int j = 0; j < 4; j++)
                    acc[i][j] += Xs[k][row_t * 4 + i] * Ys[k][col_t * 4 + j];
        }
        __syncthreads();
    }
#pragma unroll
    for (int i = 0; i < 4; i++)
#pragma unroll
        for (int j = 0; j < 4; j++)
            C[(size_t)(e0 + row_t * 4 + i) * Dd + d0 + col_t * 4 + j] = acc[i][j];
}

// ---------------- precompute: C[g][e] = sum_d A[g][d] * B[d][e]  (A·B) ----------------
__global__ __launch_bounds__(256) void ab_kernel(const float* __restrict__ A,
                                                 const float* __restrict__ B,
                                                 float* __restrict__ C) {
    __shared__ float As[16][68];
    __shared__ float Bs[16][68];
    int g0 = blockIdx.x * 64, e0 = blockIdx.y * 64;
    int tid = threadIdx.x;
    int row_t = tid >> 4, col_t = tid & 15;
    int r = tid >> 2, k4 = (tid & 3) << 2;
    int jr = tid >> 4, c4 = (tid & 15) << 2;

    float acc[4][4];
#pragma unroll
    for (int i = 0; i < 4; i++)
#pragma unroll
        for (int j = 0; j < 4; j++) acc[i][j] = 0.f;

    for (int db = 0; db < 256; db += 16) {
        float4 av = *(const float4*)(A + (size_t)(g0 + r) * Dd + db + k4);
        As[k4 + 0][r] = av.x; As[k4 + 1][r] = av.y;
        As[k4 + 2][r] = av.z; As[k4 + 3][r] = av.w;
        float4 bv = *(const float4*)(B + (size_t)(db + jr) * Dd + e0 + c4);
        Bs[jr][c4 + 0] = bv.x; Bs[jr][c4 + 1] = bv.y;
        Bs[jr][c4 + 2] = bv.z; Bs[jr][c4 + 3] = bv.w;
        __syncthreads();
#pragma unroll
        for (int k = 0; k < 16; k++) {
#pragma unroll
            for (int i = 0; i < 4; i++)
#pragma unroll
                for (int j = 0; j < 4; j++)
                    acc[i][j] += As[k][row_t * 4 + i] * Bs[k][col_t * 4 + j];
        }
        __syncthreads();
    }
#pragma unroll
    for (int i = 0; i < 4; i++)
#pragma unroll
        for (int j = 0; j < 4; j++)
            C[(size_t)(g0 + row_t * 4 + i) * Dd + e0 + col_t * 4 + j] = acc[i][j];
}

// ---------------- slots init ----------------
__global__ void slots_init_kernel(const float* __restrict__ mu,
                                  const float* __restrict__ ls,
                                  const float* __restrict__ noise) {
    int i = blockIdx.x * 256 + threadIdx.x;
    int kd = i % (Kk * Dd);
    g_slots[i] = mu[kd] + expf(ls[kd]) * noise[i];
}

// ---------------- small GEMM: C[M][Nc] = A[M][Kc] @ W[Nc][Kc]^T ----------------
__global__ __launch_bounds__(256) void small_gemm_kernel(
    const float* __restrict__ A, const float* __restrict__ W,
    const float* __restrict__ bias, const float* __restrict__ res,
    float* __restrict__ C, int Kc, int Nc, int mode)
{
    __shared__ float As[16][68];
    __shared__ float Bs[16][68];
    int m0 = blockIdx.x * 64, n0 = blockIdx.y * 64;
    int tid = threadIdx.x;
    int row_t = tid >> 4, col_t = tid & 15;
    int r = tid >> 2, k4 = (tid & 3) << 2;

    float acc[4][4];
#pragma unroll
    for (int i = 0; i < 4; i++)
#pragma unroll
        for (int j = 0; j < 4; j++) acc[i][j] = 0.f;

    for (int kb = 0; kb < Kc; kb += 16) {
        float4 av = *(const float4*)(A + (size_t)(m0 + r) * Kc + kb + k4);
        As[k4 + 0][r] = av.x; As[k4 + 1][r] = av.y;
        As[k4 + 2][r] = av.z; As[k4 + 3][r] = av.w;
        float4 wv = *(const float4*)(W + (size_t)(n0 + r) * Kc + kb + k4);
        Bs[k4 + 0][r] = wv.x; Bs[k4 + 1][r] = wv.y;
        Bs[k4 + 2][r] = wv.z; Bs[k4 + 3][r] = wv.w;
        __syncthreads();
#pragma unroll
        for (int k = 0; k < 16; k++) {
            float4 a4 = *(const float4*)&As[k][row_t * 4];
            float4 b4 = *(const float4*)&Bs[k][col_t * 4];
            float a[4] = {a4.x, a4.y, a4.z, a4.w};
            float bb[4] = {b4.x, b4.y, b4.z, b4.w};
#pragma unroll
            for (int i = 0; i < 4; i++)
#pragma unroll
                for (int j = 0; j < 4; j++) acc[i][j] += a[i] * bb[j];
        }
        __syncthreads();
    }
#pragma unroll
    for (int i = 0; i < 4; i++) {
        int m = m0 + row_t * 4 + i;
        float vals[4];
#pragma unroll
        for (int j = 0; j < 4; j++) {
            int col = n0 + col_t * 4 + j;
            float val = acc[i][j];
            if (mode & 1) val += bias[col];
            if (mode & 4) val += res[(size_t)m * Nc + col];
            if (mode & 2) val = fmaxf(val, 0.f);
            vals[j] = val;
        }
        *(float4*)(C + (size_t)m * Nc + n0 + col_t * 4) =
            make_float4(vals[0], vals[1], vals[2], vals[3]);
    }
}

// ---------------- logits (q'·x̂ᵀ) + softmax(over slots) + partial rowsums ----------------
__global__ __launch_bounds__(128) void logits_softmax_kernel(
    const float* __restrict__ q, const float* __restrict__ xln,
    float* __restrict__ attn, float* __restrict__ partsum)
{
    int b = blockIdx.y;
    int nblk = blockIdx.x;
    int tid = threadIdx.x;
    int n = nblk * 128 + tid;

    __shared__ float4 qs[Kk][64];
    const float4* qb = (const float4*)(q + (size_t)b * Kk * Dd);
    for (int i = tid; i < Kk * 64; i += 128) qs[i >> 6][i & 63] = qb[i];
    __syncthreads();

    const float4* kr = (const float4*)(xln + ((size_t)b * Nn + n) * Dd);
    float l[Kk];
#pragma unroll
    for (int s = 0; s < Kk; s++) l[s] = 0.f;
    for (int d4 = 0; d4 < 64; d4++) {
        float4 kv = kr[d4];
#pragma unroll
        for (int s = 0; s < Kk; s++) {
            float4 qv = qs[s][d4];
            l[s] += qv.x * kv.x + qv.y * kv.y + qv.z * kv.z + qv.w * kv.w;
        }
    }
    float mx = -1e30f;
#pragma unroll
    for (int s = 0; s < Kk; s++) { l[s] *= 0.0625f; mx = fmaxf(mx, l[s]); }
    float sum = 0.f;
#pragma unroll
    for (int s = 0; s < Kk; s++) { l[s] = expf(l[s] - mx); sum += l[s]; }
    float inv = 1.0f / sum;
#pragma unroll
    for (int s = 0; s < Kk; s++) {
        l[s] *= inv;
        attn[((size_t)b * Kk + s) * Nn + n] = l[s];
    }
    __shared__ float red2[Kk][4];
    int warp = tid >> 5, lane = tid & 31;
#pragma unroll
    for (int s = 0; s < Kk; s++) {
        float w = warp_sum(l[s]);
        if (lane == 0) red2[s][warp] = w;
    }
    __syncthreads();
    if (tid < Kk) {
        float s4 = red2[tid][0] + red2[tid][1] + red2[tid][2] + red2[tid][3];
        partsum[(b * Kk + tid) * NBLK + nblk] = s4;
    }
}

__global__ void invsum_kernel() {
    int i = blockIdx.x * 128 + threadIdx.x;
    if (i < BK_TOT) {
        float s = 0.f;
#pragma unroll
        for (int j = 0; j < NBLK; j++) s += g_part[i * NBLK + j];
        g_invsum[i] = 1.0f / (s + 1e-8f);
    }
}

// ---------------- u' = attn_norm @ x̂, split over 8 n-chunks ----------------
__global__ __launch_bounds__(256) void updates_partial_kernel(
    const float* __restrict__ attn, const float* __restrict__ xln)
{
    int b = blockIdx.y, chunk = blockIdx.x;
    int d = threadIdx.x;
    __shared__ float as[Kk][128];
    __shared__ float inv[Kk];
    if (d < Kk) inv[d] = g_invsum[b * Kk + d];
    float acc[Kk];
#pragma unroll
    for (int s = 0; s < Kk; s++) acc[s] = 0.f;
    int nbase = chunk * 512;
    for (int nt = 0; nt < 512; nt += 128) {
        __syncthreads();
        for (int i = d; i < Kk * 128; i += 256) {
            int s = i >> 7, nn = i & 127;
            as[s][nn] = attn[((size_t)b * Kk + s) * Nn + nbase + nt + nn] * inv[s];
        }
        __syncthreads();
#pragma unroll 4
        for (int j = 0; j < 128; j++) {
            float vv = xln[((size_t)b * Nn + nbase + nt + j) * Dd + d];
#pragma unroll
            for (int s = 0; s < Kk; s++) acc[s] += as[s][j] * vv;
        }
    }
    float* p = g_updpart + (size_t)chunk * (BK_TOT * Dd) + (size_t)(b * Kk) * Dd + d;
#pragma unroll
    for (int s = 0; s < Kk; s++) p[s * Dd] = acc[s];
}

__global__ void updates_reduce_kernel() {
    int i = blockIdx.x * 256 + threadIdx.x;
    float s = 0.f;
#pragma unroll
    for (int c = 0; c < 8; c++) s += g_updpart[(size_t)c * (BK_TOT * Dd) + i];
    g_updates[i] = s;
}

// ---------------- GRU gates ----------------
__global__ void gru_gate_kernel() {
    int i = blockIdx.x * 256 + threadIdx.x;
    int row = i >> 8, d = i & 255;
    const float* gi = g_gi + (size_t)row * 768;
    const float* gh = g_gh + (size_t)row * 768;
    float r = sigmoidf_(gi[d] + gh[d]);
    float z = sigmoidf_(gi[256 + d] + gh[256 + d]);
    float nn = tanhf(gi[512 + d] + r * gh[512 + d]);
    float h = g_slots_prev[i];
    g_slots[i] = (1.0f - z) * nn + z * h;
}

__global__ void copy_kernel(const float* __restrict__ src, float* __restrict__ dst, int n) {
    int i = blockIdx.x * 256 + threadIdx.x;
    if (i < n) dst[i] = src[i];
}

// ---------------- host orchestration ----------------
extern "C" void kernel_launch(void* const* d_in, const int* in_sizes, int n_in,
                              void* d_out, int out_size) {
    const float* inputs        = (const float*)d_in[0];
    const float* slot_noise    = (const float*)d_in[1];
    const float* slots_mu      = (const float*)d_in[2];
    const float* slots_logsig  = (const float*)d_in[3];
    const float* Wq            = (const float*)d_in[4];
    const float* Wk            = (const float*)d_in[5];
    const float* Wv            = (const float*)d_in[6];
    const float* w_ih          = (const float*)d_in[7];
    const float* w_hh          = (const float*)d_in[8];
    const float* b_ih          = (const float*)d_in[9];
    const float* b_hh          = (const float*)d_in[10];
    const float* mlp_w1        = (const float*)d_in[11];
    const float* mlp_b1        = (const float*)d_in[12];
    const float* mlp_w2        = (const float*)d_in[13];
    const float* mlp_b2        = (const float*)d_in[14];
    const float* ln_in_w       = (const float*)d_in[15];
    const float* ln_in_b       = (const float*)d_in[16];
    const float* ln_s_w        = (const float*)d_in[17];
    const float* ln_s_b        = (const float*)d_in[18];
    const float* ln_m_w        = (const float*)d_in[19];
    const float* ln_m_b        = (const float*)d_in[20];
    float* out = (float*)d_out;

    float *p_xln, *p_wqk, *p_wiv, *p_attn, *p_part, *p_sln, *p_q, *p_slots,
          *p_prev, *p_upd, *p_gi, *p_gh, *p_h1;
    cudaGetSymbolAddress((void**)&p_xln, g_xln);
    cudaGetSymbolAddress((void**)&p_wqk, g_wqk);
    cudaGetSymbolAddress((void**)&p_wiv, g_wiv);
    cudaGetSymbolAddress((void**)&p_attn, g_attn);
    cudaGetSymbolAddress((void**)&p_part, g_part);
    cudaGetSymbolAddress((void**)&p_sln, g_sln);
    cudaGetSymbolAddress((void**)&p_q, g_q);
    cudaGetSymbolAddress((void**)&p_slots, g_slots);
    cudaGetSymbolAddress((void**)&p_prev, g_slots_prev);
    cudaGetSymbolAddress((void**)&p_upd, g_updates);
    cudaGetSymbolAddress((void**)&p_gi, g_gi);
    cudaGetSymbolAddress((void**)&p_gh, g_gh);
    cudaGetSymbolAddress((void**)&p_h1, g_h1);

    // x̂ = LN(inputs); weight folds; slots init
    ln_apply_kernel<<<BN_TOT / 8, dim3(32, 8)>>>(inputs, p_xln, ln_in_w, ln_in_b, BN_TOT);
    atb_kernel<<<dim3(4, 4), 256>>>(Wk, Wq, p_wqk);        // Wqk[e][d] = Σ_j Wk[j,e]·Wq[j,d]
    ab_kernel<<<dim3(12, 4), 256>>>(w_ih, Wv, p_wiv);      // W_iv[g][e] = Σ_d w_ih[g,d]·Wv[d,e]
    slots_init_kernel<<<BK_TOT, 256>>>(slots_mu, slots_logsig, slot_noise);

    for (int it = 0; it < 3; it++) {
        copy_kernel<<<960, 256>>>(p_slots, p_prev, BK_TOT * Dd);
        ln_apply_kernel<<<120, dim3(32, 8)>>>(p_slots, p_sln, ln_s_w, ln_s_b, BK_TOT);
        small_gemm_kernel<<<dim3(15, 4), 256>>>(p_sln, p_wqk, nullptr, nullptr, p_q, 256, 256, 0);
        logits_softmax_kernel<<<dim3(NBLK, Bb), 128>>>(p_q, p_xln, p_attn, p_part);
        invsum_kernel<<<8, 128>>>();
        updates_partial_kernel<<<dim3(8, Bb), 256>>>(p_attn, p_xln);
        updates_reduce_kernel<<<960, 256>>>();
        small_gemm_kernel<<<dim3(15, 12), 256>>>(p_upd, p_wiv, b_ih, nullptr, p_gi, 256, 768, 1);
        small_gemm_kernel<<<dim3(15, 12), 256>>>(p_prev, w_hh, b_hh, nullptr, p_gh, 256, 768, 1);
        gru_gate_kernel<<<960, 256>>>();
        ln_apply_kernel<<<120, dim3(32, 8)>>>(p_slots, p_sln, ln_m_w, ln_m_b, BK_TOT);
        small_gemm_kernel<<<dim3(15, 8), 256>>>(p_sln, mlp_w1, mlp_b1, nullptr, p_h1, 256, 512, 1 | 2);
        small_gemm_kernel<<<dim3(15, 4), 256>>>(p_h1, mlp_w2, mlp_b2, p_slots, p_slots, 512, 256, 1 | 4);
    }

    // final attention
    ln_apply_kernel<<<120, dim3(32, 8)>>>(p_slots, p_sln, ln_s_w, ln_s_b, BK_TOT);
    small_gemm_kernel<<<dim3(15, 4), 256>>>(p_sln, p_wqk, nullptr, nullptr, p_q, 256, 256, 0);
    logits_softmax_kernel<<<dim3(NBLK, Bb), 128>>>(p_q, p_xln, out + BK_TOT * Dd, p_part);
    copy_kernel<<<960, 256>>>(p_slots, out, BK_TOT * Dd);
}